// round 9
// baseline (speedup 1.0000x reference)
#include <cuda_runtime.h>
#include <math.h>

// ---------------------------------------------------------------------------
// LSForward: Born-series scattering, M=4096 pts, 4 wavenumbers (0.5*m), 5 iters.
// R9: symmetric rotation scheme (verified correct in R8: R3-exact e-form) with
// finer work decomposition. R8 was latency-bound at 14.7 warps/SM (occ 19.3%,
// issue 63.9%); fix = 2 j-contexts per warp -> 4224 warps (28.5/SM), with the
// fixed j-contexts offloaded to per-warp SMEM slices so registers fit
// (launch_bounds(64,14), cap 73). fma work unchanged (~19.6us/SM ideal).
// ---------------------------------------------------------------------------

constexpr int M_PTS  = 4096;
constexpr int NDOBS  = 64;
constexpr int NK     = 4;
constexpr int N_ITER = 5;

constexpr int NWR      = 128;                 // warp-rows of 32
constexpr int NCH      = 32;                  // delta-chunks of 2 (deltas 1..64)
constexpr int UNITS_A  = NCH + 1;             // + diagonal unit = 33
constexpr int NUNITS   = NWR * UNITS_A;       // 4224 warp-units
constexpr int NBLK_ACC = NUNITS / 2;          // 2112 blocks of 64 (2 warps)

constexpr float C_G = 0.07957747154594767f;   // 1/(4*pi)

// Scratch (allocation-free __device__ globals)
__device__ float g_px[M_PTS], g_py[M_PTS], g_pz[M_PTS];
__device__ float g_r2q[M_PTS];                    // 0.25*|p|^2
__device__ float g_vw[M_PTS];                     // 0.5*C_G * V * w (folded)
__device__ float g_p0[NK * 2 * M_PTS];
__device__ float g_p [NK * 2 * M_PTS];
__device__ float g_a [NK * 2 * M_PTS];            // folded matvec input
__device__ float g_ipart[NWR][NCH][32][8];        // i-side partials (4 MB)
__device__ float g_jpart[NWR][65][32][8];         // j-side partials, idx=delta (8.5 MB)

__device__ __forceinline__ float fsqrt_approx(float x) {
    float r; asm("sqrt.approx.f32 %0,%1;" : "=f"(r) : "f"(x)); return r;
}
__device__ __forceinline__ float fdouble_alu(float x) {
    // exact 2*x for normal floats via exponent increment (alu pipe)
    return __int_as_float(__float_as_int(x) + 0x00800000);
}
__device__ __forceinline__ void pdl_wait() {
#if __CUDA_ARCH__ >= 900
    cudaGridDependencySynchronize();
#endif
}

// ---------------------------------------------------------------------------
__global__ void k_init(const float* __restrict__ V,
                       const float* __restrict__ pts,
                       const float* __restrict__ w) {
    int i = blockIdx.x * blockDim.x + threadIdx.x;
    if (i >= M_PTS) return;
    float x = pts[3 * i], y = pts[3 * i + 1], z = pts[3 * i + 2];
    g_px[i] = x; g_py[i] = y; g_pz[i] = z;
    g_r2q[i] = 0.25f * (x * x + y * y + z * z);
    float vw = 0.5f * C_G * V[i] * w[i];
    g_vw[i] = vw;
#pragma unroll
    for (int m = 0; m < NK; m++) {
        float kv = 0.5f * (float)(m + 1);
        float s, c;
        sincosf(kv * z, &s, &c);
        g_p0[m * 2 * M_PTS + i]          = c;
        g_p0[m * 2 * M_PTS + M_PTS + i]  = s;
        g_p [m * 2 * M_PTS + i]          = c;
        g_p [m * 2 * M_PTS + M_PTS + i]  = s;
        g_a [m * 2 * M_PTS + i]          = vw * c;
        g_a [m * 2 * M_PTS + M_PTS + i]  = vw * s;
    }
}

// ---------------------------------------------------------------------------
// Symmetric Born matvec. warp-unit = (a, sub); sub<32: 2 off-diag tiles
// delta = 2*sub+1, 2*sub+2 (dual-side, j-context in smem); sub==32: diagonal
// tile (single-side). e-form matches R3 EXACTLY (numerically load-bearing).
// ---------------------------------------------------------------------------
__global__ __launch_bounds__(64, 14) void k_acc() {
    __shared__ float4 s_jp[2][2][32];       // [warpInBlk][ctx][lane] pos+r2q
    __shared__ float4 s_ja[2][2][2][32];    // [warpInBlk][ctx][half][lane] a

    pdl_wait();

    int w    = threadIdx.x >> 5;
    int lane = threadIdx.x & 31;
    int unit = blockIdx.x * 2 + w;
    int a    = unit / UNITS_A;
    int sub  = unit - a * UNITS_A;
    int src  = (lane + 1) & 31;             // rotation source lane

    // rotating i-context: row i0 = 32a + lane
    int i0 = 32 * a + lane;
    float Rpx = g_px[i0], Rpy = g_py[i0], Rpz = g_pz[i0], Rr2 = g_r2q[i0];
    float Rar[NK], Rai[NK];
#pragma unroll
    for (int m = 0; m < NK; m++) {
        Rar[m] = g_a[m * 2 * M_PTS + i0];
        Rai[m] = g_a[m * 2 * M_PTS + M_PTS + i0];
    }

    if (sub < NCH) {
        // ---- dual-side: 2 fixed j-contexts (SMEM) sharing one rotation ----
        int  brow[2]; bool valid[2];
#pragma unroll
        for (int t = 0; t < 2; t++) {
            int d  = 2 * sub + 1 + t;
            bool v = (d < 64) || (a < 64);          // delta==64 only for a<64
            int b  = (a + d) & (NWR - 1);
            brow[t] = b; valid[t] = v;
            int j = 32 * b + lane;
            s_jp[w][t][lane] = make_float4(g_px[j], g_py[j], g_pz[j], g_r2q[j]);
            float4 a0, a1;
            if (v) {
                a0 = make_float4(g_a[j],                 g_a[M_PTS + j],
                                 g_a[2 * M_PTS + j],     g_a[3 * M_PTS + j]);
                a1 = make_float4(g_a[4 * M_PTS + j],     g_a[5 * M_PTS + j],
                                 g_a[6 * M_PTS + j],     g_a[7 * M_PTS + j]);
            } else {
                a0 = make_float4(0.f, 0.f, 0.f, 0.f);
                a1 = a0;
            }
            s_ja[w][t][0][lane] = a0;
            s_ja[w][t][1][lane] = a1;
        }
        __syncwarp();                                // per-warp smem slice

        float Jacr[2][NK], Jaci[2][NK];
        float Racr[NK] = {0.f, 0.f, 0.f, 0.f};
        float Raci[NK] = {0.f, 0.f, 0.f, 0.f};
#pragma unroll
        for (int t = 0; t < 2; t++)
#pragma unroll
            for (int m = 0; m < NK; m++) { Jacr[t][m] = 0.f; Jaci[t][m] = 0.f; }

#pragma unroll 1
        for (int o = 0; o < 32; o++) {
#pragma unroll
            for (int t = 0; t < 2; t++) {
                float4 P  = s_jp[w][t][lane];
                float4 A0 = s_ja[w][t][0][lane];
                float4 A1 = s_ja[w][t][1][lane];
                // R3-exact distance form (numerically load-bearing!)
                float dot = fmaf(Rpx, P.x, fmaf(Rpy, P.y, Rpz * P.z));
                float e   = fmaf(-0.5f, dot, Rr2 + P.w);      // 0.25*d2
                e = fmaxf(e, 2.5e-13f);
                float th = fsqrt_approx(e);           // 0.5*D
                float sc = rsqrtf(e);                 // 2/D (scale folded in a)
                float s1, c1;
                __sincosf(th, &s1, &c1);
                float tc  = fdouble_alu(c1);
                float g1r = sc * c1,             g1i = sc * s1;
                float g2r = fmaf(tc, g1r, -sc);  float g2i = tc * g1i;
                float g3r = fmaf(tc, g2r, -g1r); float g3i = fmaf(tc, g2i, -g1i);
                float g4r = fmaf(tc, g3r, -g2r); float g4i = fmaf(tc, g3i, -g2i);
                // j-side: out(j) += G * a(i_rot); i-side: out(i_rot) += G * a(j)
                Jacr[t][0] = fmaf(g1r, Rar[0], fmaf(-g1i, Rai[0], Jacr[t][0]));
                Jaci[t][0] = fmaf(g1r, Rai[0], fmaf( g1i, Rar[0], Jaci[t][0]));
                Racr[0]    = fmaf(g1r, A0.x,   fmaf(-g1i, A0.y,   Racr[0]));
                Raci[0]    = fmaf(g1r, A0.y,   fmaf( g1i, A0.x,   Raci[0]));
                Jacr[t][1] = fmaf(g2r, Rar[1], fmaf(-g2i, Rai[1], Jacr[t][1]));
                Jaci[t][1] = fmaf(g2r, Rai[1], fmaf( g2i, Rar[1], Jaci[t][1]));
                Racr[1]    = fmaf(g2r, A0.z,   fmaf(-g2i, A0.w,   Racr[1]));
                Raci[1]    = fmaf(g2r, A0.w,   fmaf( g2i, A0.z,   Raci[1]));
                Jacr[t][2] = fmaf(g3r, Rar[2], fmaf(-g3i, Rai[2], Jacr[t][2]));
                Jaci[t][2] = fmaf(g3r, Rai[2], fmaf( g3i, Rar[2], Jaci[t][2]));
                Racr[2]    = fmaf(g3r, A1.x,   fmaf(-g3i, A1.y,   Racr[2]));
                Raci[2]    = fmaf(g3r, A1.y,   fmaf( g3i, A1.x,   Raci[2]));
                Jacr[t][3] = fmaf(g4r, Rar[3], fmaf(-g4i, Rai[3], Jacr[t][3]));
                Jaci[t][3] = fmaf(g4r, Rai[3], fmaf( g4i, Rar[3], Jaci[t][3]));
                Racr[3]    = fmaf(g4r, A1.z,   fmaf(-g4i, A1.w,   Racr[3]));
                Raci[3]    = fmaf(g4r, A1.w,   fmaf( g4i, A1.z,   Raci[3]));
            }
            // rotate i-context (pos + a + acc) by one lane
            Rpx = __shfl_sync(0xffffffffu, Rpx, src);
            Rpy = __shfl_sync(0xffffffffu, Rpy, src);
            Rpz = __shfl_sync(0xffffffffu, Rpz, src);
            Rr2 = __shfl_sync(0xffffffffu, Rr2, src);
#pragma unroll
            for (int m = 0; m < NK; m++) {
                Rar[m]  = __shfl_sync(0xffffffffu, Rar[m],  src);
                Rai[m]  = __shfl_sync(0xffffffffu, Rai[m],  src);
                Racr[m] = __shfl_sync(0xffffffffu, Racr[m], src);
                Raci[m] = __shfl_sync(0xffffffffu, Raci[m], src);
            }
        }
        // 32 rotations -> i-acc back home. Flush.
#pragma unroll
        for (int m = 0; m < NK; m++) {
            g_ipart[a][sub][lane][2 * m]     = Racr[m];
            g_ipart[a][sub][lane][2 * m + 1] = Raci[m];
        }
#pragma unroll
        for (int t = 0; t < 2; t++) {
            if (valid[t]) {
                int d = 2 * sub + 1 + t;
#pragma unroll
                for (int m = 0; m < NK; m++) {
                    g_jpart[brow[t]][d][lane][2 * m]     = Jacr[t][m];
                    g_jpart[brow[t]][d][lane][2 * m + 1] = Jaci[t][m];
                }
            }
        }
    } else {
        // ---- diagonal tile (a,a): single-side, skip i==j (o starts at 1) ----
        float Jpx = Rpx, Jpy = Rpy, Jpz = Rpz, Jr2 = Rr2;
        float Jacr[NK], Jaci[NK];
#pragma unroll
        for (int m = 0; m < NK; m++) { Jacr[m] = 0.f; Jaci[m] = 0.f; }
#pragma unroll 1
        for (int o = 1; o < 32; o++) {
            // rotate first (skip o=0 self pair)
            Rpx = __shfl_sync(0xffffffffu, Rpx, src);
            Rpy = __shfl_sync(0xffffffffu, Rpy, src);
            Rpz = __shfl_sync(0xffffffffu, Rpz, src);
            Rr2 = __shfl_sync(0xffffffffu, Rr2, src);
#pragma unroll
            for (int m = 0; m < NK; m++) {
                Rar[m] = __shfl_sync(0xffffffffu, Rar[m], src);
                Rai[m] = __shfl_sync(0xffffffffu, Rai[m], src);
            }
            float dot = fmaf(Rpx, Jpx, fmaf(Rpy, Jpy, Rpz * Jpz));
            float e   = fmaf(-0.5f, dot, Rr2 + Jr2);          // 0.25*d2
            e = fmaxf(e, 2.5e-13f);
            float th = fsqrt_approx(e);
            float sc = rsqrtf(e);
            float s1, c1;
            __sincosf(th, &s1, &c1);
            float tc  = fdouble_alu(c1);
            float g1r = sc * c1,             g1i = sc * s1;
            float g2r = fmaf(tc, g1r, -sc);  float g2i = tc * g1i;
            float g3r = fmaf(tc, g2r, -g1r); float g3i = fmaf(tc, g2i, -g1i);
            float g4r = fmaf(tc, g3r, -g2r); float g4i = fmaf(tc, g3i, -g2i);
            float gr[NK] = {g1r, g2r, g3r, g4r};
            float gi[NK] = {g1i, g2i, g3i, g4i};
#pragma unroll
            for (int m = 0; m < NK; m++) {
                Jacr[m] = fmaf(gr[m], Rar[m], fmaf(-gi[m], Rai[m], Jacr[m]));
                Jaci[m] = fmaf(gr[m], Rai[m], fmaf( gi[m], Rar[m], Jaci[m]));
            }
        }
#pragma unroll
        for (int m = 0; m < NK; m++) {
            g_jpart[a][0][lane][2 * m]     = Jacr[m];
            g_jpart[a][0][lane][2 * m + 1] = Jaci[m];
        }
    }
}

// ---------------------------------------------------------------------------
// Deterministic reduction + Born update: p = p0 + sum; a = vw*p.
// One thread per (row, slot); fixed summation order.
// ---------------------------------------------------------------------------
__global__ void k_update() {
    pdl_wait();
    int idx  = blockIdx.x * blockDim.x + threadIdx.x;   // 0 .. 32767
    int slot = idx & 7;
    int r    = idx >> 3;
    int c = r >> 5, l = r & 31;
    float s = 0.f;
#pragma unroll 4
    for (int ch = 0; ch < NCH; ch++) s += g_ipart[c][ch][l][slot];
#pragma unroll 4
    for (int d = 0; d < 64; d++)     s += g_jpart[c][d][l][slot];
    if (c >= 64)                      s += g_jpart[c][64][l][slot];
    int m = slot >> 1, ci = slot & 1;
    int e = m * 2 * M_PTS + ci * M_PTS + r;
    float pv = g_p0[e] + s;
    g_p[e] = pv;
    g_a[e] = g_vw[r] * pv;
}

// ---------------------------------------------------------------------------
// Far-field: one block per observation direction.
// ---------------------------------------------------------------------------
__global__ __launch_bounds__(256) void k_far(const float* __restrict__ V,
                                             const float* __restrict__ obs,
                                             const float* __restrict__ w,
                                             float* __restrict__ out) {
    constexpr int FTPB = 256;
    pdl_wait();
    int d = blockIdx.x;
    int t = threadIdx.x;
    float ox = obs[3 * d], oy = obs[3 * d + 1], oz = obs[3 * d + 2];

    float fr[NK] = {0.f, 0.f, 0.f, 0.f};
    float fi[NK] = {0.f, 0.f, 0.f, 0.f};

    for (int j = t; j < M_PTS; j += FTPB) {
        float q = fmaf(g_px[j], ox, fmaf(g_py[j], oy, g_pz[j] * oz));
        float s1, c1;
        __sincosf(0.5f * q, &s1, &c1);
        float tc = c1 + c1;
        float cm[NK], sm[NK];
        cm[0] = c1;                      sm[0] = s1;
        cm[1] = fmaf(tc, c1, -1.f);      sm[1] = tc * s1;
        cm[2] = fmaf(tc, cm[1], -cm[0]); sm[2] = fmaf(tc, sm[1], -sm[0]);
        cm[3] = fmaf(tc, cm[2], -cm[1]); sm[3] = fmaf(tc, sm[2], -sm[1]);
        float v = V[j], wj = w[j];
#pragma unroll
        for (int m = 0; m < NK; m++) {
            float pr = g_p[m * 2 * M_PTS + j];
            float pi = g_p[m * 2 * M_PTS + M_PTS + j];
            float zr = v * pr, zi = v * pi;
            float ir = fmaf(zr, cm[m],  zi * sm[m]);   // exp(-ikQ)
            float ii = fmaf(zi, cm[m], -zr * sm[m]);
            fr[m] = fmaf(wj, ir, fr[m]);
            fi[m] = fmaf(wj, ii, fi[m]);
        }
    }

#pragma unroll
    for (int off = 16; off; off >>= 1) {
#pragma unroll
        for (int m = 0; m < NK; m++) {
            fr[m] += __shfl_down_sync(0xffffffffu, fr[m], off);
            fi[m] += __shfl_down_sync(0xffffffffu, fi[m], off);
        }
    }
    __shared__ float sred[8][FTPB / 32];
    int lane = t & 31, wid = t >> 5;
    if (lane == 0) {
#pragma unroll
        for (int m = 0; m < NK; m++) {
            sred[2 * m][wid]     = fr[m];
            sred[2 * m + 1][wid] = fi[m];
        }
    }
    __syncthreads();
    if (t < 8) {
        float s = 0.f;
#pragma unroll
        for (int wdx = 0; wdx < FTPB / 32; wdx++) s += sred[t][wdx];
        int m = t >> 1, c = t & 1;
        out[m * NDOBS * 2 + d * 2 + c] = -C_G * s;
    }
}

// ---------------------------------------------------------------------------
template <typename K, typename... Args>
static inline void launch_pdl(K kernel, dim3 grid, dim3 block, Args... args) {
    cudaLaunchConfig_t cfg = {};
    cfg.gridDim = grid;
    cfg.blockDim = block;
    cfg.dynamicSmemBytes = 0;
    cfg.stream = 0;
    cudaLaunchAttribute at[1];
    at[0].id = cudaLaunchAttributeProgrammaticStreamSerialization;
    at[0].val.programmaticStreamSerializationAllowed = 1;
    cfg.attrs = at;
    cfg.numAttrs = 1;
    cudaLaunchKernelEx(&cfg, kernel, args...);
}

extern "C" void kernel_launch(void* const* d_in, const int* in_sizes, int n_in,
                              void* d_out, int out_size) {
    const float* V   = (const float*)d_in[0];   // [4096]
    const float* obs = (const float*)d_in[1];   // [64,3]
    const float* pts = (const float*)d_in[2];   // [4096,3]
    const float* w   = (const float*)d_in[3];   // [4096]
    float* out = (float*)d_out;                 // [4,64,2]

    k_init<<<M_PTS / 256, 256>>>(V, pts, w);
    for (int it = 0; it < N_ITER; it++) {
        launch_pdl(k_acc, dim3(NBLK_ACC), dim3(64));
        launch_pdl(k_update, dim3(128), dim3(256));
    }
    launch_pdl(k_far, dim3(NDOBS), dim3(256), V, obs, w, out);
}

// round 10
// speedup vs baseline: 1.7806x; 1.7806x over previous
#include <cuda_runtime.h>
#include <math.h>

// ---------------------------------------------------------------------------
// LSForward: Born-series scattering, M=4096 pts, 4 wavenumbers (0.5*m), 5 iters.
// R10 = R3 (best verified: 170.5us, acc at ~97% of the 3-reg FFMA ceiling)
// plus ONLY the two levers proven output-neutral by the R4==R7 experiment:
//   (1) PDL on all chained launches (kills ~1.5us/launch-gap x 11);
//   (2) tc = 2*c1 via exact exponent-increment on the alu pipe (frees 1 of 30
//       fma-pipe slots per pair).
// Symmetric-pair scheme abandoned: its -22% fma ops is always eaten by the
// shfl-chain serialization (issue capped ~62% in R8/R9 vs 76.5% here).
// ---------------------------------------------------------------------------

constexpr int M_PTS  = 4096;
constexpr int NDOBS  = 64;
constexpr int NK     = 4;
constexpr int N_ITER = 5;

constexpr int TPB    = 128;                    // threads per block
constexpr int RPT    = 2;                      // rows per thread
constexpr int ROWBLK = M_PTS / (TPB * RPT);    // 16 row-blocks
constexpr int JSPLIT = 64;                     // j-partition count (grid.y)
constexpr int JCHUNK = M_PTS / JSPLIT;         // 64 j's per block

constexpr float C_G = 0.07957747154594767f;    // 1/(4*pi)

// Scratch (allocation-free: __device__ globals)
__device__ float g_px[M_PTS], g_py[M_PTS], g_pz[M_PTS];
__device__ float g_r2q[M_PTS];                     // 0.25*|p|^2
__device__ float g_vw[M_PTS];                      // 0.5*C_G * V * w (folded)
__device__ float g_p0[NK * 2 * M_PTS];
__device__ float g_p [NK * 2 * M_PTS];
__device__ float g_a [NK * 2 * M_PTS];             // folded matvec input
__device__ float g_part[JSPLIT][NK * 2 * M_PTS];   // deterministic j-partials (8 MB)

__device__ __forceinline__ float fsqrt_approx(float x) {
    float r; asm("sqrt.approx.f32 %0,%1;" : "=f"(r) : "f"(x)); return r;
}
__device__ __forceinline__ float fdouble_alu(float x) {
    // exact 2*x for normal floats via exponent increment (alu pipe; proven
    // output-neutral by R4==R7). Frees one fma-pipe slot per pair.
    return __int_as_float(__float_as_int(x) + 0x00800000);
}
__device__ __forceinline__ void pdl_wait() {
#if __CUDA_ARCH__ >= 900
    cudaGridDependencySynchronize();
#endif
}

// ---------------------------------------------------------------------------
__global__ void k_init(const float* __restrict__ V,
                       const float* __restrict__ pts,
                       const float* __restrict__ w) {
    int i = blockIdx.x * blockDim.x + threadIdx.x;
    if (i >= M_PTS) return;
    float x = pts[3 * i], y = pts[3 * i + 1], z = pts[3 * i + 2];
    g_px[i] = x; g_py[i] = y; g_pz[i] = z;
    g_r2q[i] = 0.25f * (x * x + y * y + z * z);
    float vw = 0.5f * C_G * V[i] * w[i];
    g_vw[i] = vw;
#pragma unroll
    for (int m = 0; m < NK; m++) {
        float kv = 0.5f * (float)(m + 1);
        float s, c;
        sincosf(kv * z, &s, &c);                   // accurate; one-time cost
        g_p0[m * 2 * M_PTS + i]          = c;
        g_p0[m * 2 * M_PTS + M_PTS + i]  = s;
        g_p [m * 2 * M_PTS + i]          = c;
        g_p [m * 2 * M_PTS + M_PTS + i]  = s;
        g_a [m * 2 * M_PTS + i]          = vw * c;
        g_a [m * 2 * M_PTS + M_PTS + i]  = vw * s;
    }
}

// ---------------------------------------------------------------------------
// Core Born matvec: grid (ROWBLK, JSPLIT), 256 rows x 64 j per block.
// Per pair: e = 0.25*d2 (R3-exact form: dot first, then ONE fused
// -0.5*dot + r2sum — numerically load-bearing near coincident points);
// theta = sqrt(e) = 0.5*D; sc = rsqrt(e) = 2/D with 0.5*C_G prefolded in a.
// Chebyshev G_m = sc * exp(i*m*theta).
// ---------------------------------------------------------------------------
__global__ __launch_bounds__(TPB) void k_acc() {
    __shared__ alignas(16) float sj[JCHUNK][12];  // px,py,pz,r2q, ar0,ai0..ar3,ai3

    pdl_wait();                                   // g_a/g_px from predecessor

    int t  = threadIdx.x;
    int j0 = blockIdx.y * JCHUNK;

    if (t < JCHUNK) {
        int j = j0 + t;
        sj[t][0] = g_px[j];
        sj[t][1] = g_py[j];
        sj[t][2] = g_pz[j];
        sj[t][3] = g_r2q[j];
#pragma unroll
        for (int m = 0; m < NK; m++) {
            sj[t][4 + 2 * m] = g_a[m * 2 * M_PTS + j];
            sj[t][5 + 2 * m] = g_a[m * 2 * M_PTS + M_PTS + j];
        }
    }
    __syncthreads();

    int rbase = blockIdx.x * (TPB * RPT) + t;
    float pix[RPT], piy[RPT], piz[RPT], r2i[RPT];
#pragma unroll
    for (int r = 0; r < RPT; r++) {
        int row = rbase + r * TPB;
        pix[r] = g_px[row]; piy[r] = g_py[row];
        piz[r] = g_pz[row]; r2i[r] = g_r2q[row];
    }

    float accr[RPT][NK], acci[RPT][NK];
#pragma unroll
    for (int r = 0; r < RPT; r++)
#pragma unroll
        for (int m = 0; m < NK; m++) { accr[r][m] = 0.f; acci[r][m] = 0.f; }

#pragma unroll 2
    for (int jj = 0; jj < JCHUNK; jj++) {
        float4 P  = *reinterpret_cast<const float4*>(&sj[jj][0]);
        float4 A0 = *reinterpret_cast<const float4*>(&sj[jj][4]);
        float4 A1 = *reinterpret_cast<const float4*>(&sj[jj][8]);
        int jg = j0 + jj;
#pragma unroll
        for (int r = 0; r < RPT; r++) {
            int row = rbase + r * TPB;
            float dot = fmaf(pix[r], P.x, fmaf(piy[r], P.y, piz[r] * P.z));
            float e   = fmaf(-0.5f, dot, r2i[r] + P.w);     // 0.25 * d2
            e = fmaxf(e, 2.5e-13f);
            float th  = fsqrt_approx(e);                    // 0.5 * D
            float sc  = rsqrtf(e);                          // 2/D (scale in a)
            sc = (row == jg) ? 0.f : sc;
            float s1, c1;
            __sincosf(th, &s1, &c1);
            float tc  = fdouble_alu(c1);                    // 2*c1, alu pipe
            // Chebyshev: G_m = sc * exp(i m theta)
            float g1r = sc * c1,             g1i = sc * s1;
            float g2r = fmaf(tc, g1r, -sc);  float g2i = tc * g1i;
            float g3r = fmaf(tc, g2r, -g1r); float g3i = fmaf(tc, g2i, -g1i);
            float g4r = fmaf(tc, g3r, -g2r); float g4i = fmaf(tc, g3i, -g2i);
            // complex MAC (negations free in FFMA modifiers)
            accr[r][0] = fmaf(g1r, A0.x, fmaf(-g1i, A0.y, accr[r][0]));
            acci[r][0] = fmaf(g1r, A0.y, fmaf( g1i, A0.x, acci[r][0]));
            accr[r][1] = fmaf(g2r, A0.z, fmaf(-g2i, A0.w, accr[r][1]));
            acci[r][1] = fmaf(g2r, A0.w, fmaf( g2i, A0.z, acci[r][1]));
            accr[r][2] = fmaf(g3r, A1.x, fmaf(-g3i, A1.y, accr[r][2]));
            acci[r][2] = fmaf(g3r, A1.y, fmaf( g3i, A1.x, acci[r][2]));
            accr[r][3] = fmaf(g4r, A1.z, fmaf(-g4i, A1.w, accr[r][3]));
            acci[r][3] = fmaf(g4r, A1.w, fmaf( g4i, A1.z, acci[r][3]));
        }
    }

    float* part = g_part[blockIdx.y];
#pragma unroll
    for (int r = 0; r < RPT; r++) {
        int row = rbase + r * TPB;
#pragma unroll
        for (int m = 0; m < NK; m++) {
            part[m * 2 * M_PTS + row]         = accr[r][m];
            part[m * 2 * M_PTS + M_PTS + row] = acci[r][m];
        }
    }
}

// ---------------------------------------------------------------------------
// Deterministic partial reduction + Born update: p = p0 + sum; a = vw*p.
// ---------------------------------------------------------------------------
__global__ void k_update() {
    pdl_wait();                                  // g_part from k_acc
    int e = blockIdx.x * blockDim.x + threadIdx.x;  // 0 .. NK*2*M-1
    float s = 0.f;
#pragma unroll 8
    for (int js = 0; js < JSPLIT; js++) s += g_part[js][e];
    float pv = g_p0[e] + s;
    g_p[e] = pv;
    g_a[e] = g_vw[e & (M_PTS - 1)] * pv;         // vw already 0.5*C_G*V*w
}

// ---------------------------------------------------------------------------
// Far-field: one block per observation direction.
// ---------------------------------------------------------------------------
__global__ __launch_bounds__(256) void k_far(const float* __restrict__ V,
                                             const float* __restrict__ obs,
                                             const float* __restrict__ w,
                                             float* __restrict__ out) {
    constexpr int FTPB = 256;
    pdl_wait();                                  // g_p from final k_update
    int d = blockIdx.x;
    int t = threadIdx.x;
    float ox = obs[3 * d], oy = obs[3 * d + 1], oz = obs[3 * d + 2];

    float fr[NK] = {0.f, 0.f, 0.f, 0.f};
    float fi[NK] = {0.f, 0.f, 0.f, 0.f};

    for (int j = t; j < M_PTS; j += FTPB) {
        float q = fmaf(g_px[j], ox, fmaf(g_py[j], oy, g_pz[j] * oz));
        float s1, c1;
        __sincosf(0.5f * q, &s1, &c1);
        float tc = c1 + c1;
        float cm[NK], sm[NK];
        cm[0] = c1;                      sm[0] = s1;
        cm[1] = fmaf(tc, c1, -1.f);      sm[1] = tc * s1;
        cm[2] = fmaf(tc, cm[1], -cm[0]); sm[2] = fmaf(tc, sm[1], -sm[0]);
        cm[3] = fmaf(tc, cm[2], -cm[1]); sm[3] = fmaf(tc, sm[2], -sm[1]);
        float v = V[j], wj = w[j];
#pragma unroll
        for (int m = 0; m < NK; m++) {
            float pr = g_p[m * 2 * M_PTS + j];
            float pi = g_p[m * 2 * M_PTS + M_PTS + j];
            float zr = v * pr, zi = v * pi;
            float ir = fmaf(zr, cm[m],  zi * sm[m]);   // exp(-ikQ)
            float ii = fmaf(zi, cm[m], -zr * sm[m]);
            fr[m] = fmaf(wj, ir, fr[m]);
            fi[m] = fmaf(wj, ii, fi[m]);
        }
    }

#pragma unroll
    for (int off = 16; off; off >>= 1) {
#pragma unroll
        for (int m = 0; m < NK; m++) {
            fr[m] += __shfl_down_sync(0xffffffffu, fr[m], off);
            fi[m] += __shfl_down_sync(0xffffffffu, fi[m], off);
        }
    }
    __shared__ float sred[8][FTPB / 32];
    int lane = t & 31, wid = t >> 5;
    if (lane == 0) {
#pragma unroll
        for (int m = 0; m < NK; m++) {
            sred[2 * m][wid]     = fr[m];
            sred[2 * m + 1][wid] = fi[m];
        }
    }
    __syncthreads();
    if (t < 8) {
        float s = 0.f;
#pragma unroll
        for (int wdx = 0; wdx < FTPB / 32; wdx++) s += sred[t][wdx];
        int m = t >> 1, c = t & 1;
        out[m * NDOBS * 2 + d * 2 + c] = -C_G * s;
    }
}

// ---------------------------------------------------------------------------
template <typename K, typename... Args>
static inline void launch_pdl(K kernel, dim3 grid, dim3 block, Args... args) {
    cudaLaunchConfig_t cfg = {};
    cfg.gridDim = grid;
    cfg.blockDim = block;
    cfg.dynamicSmemBytes = 0;
    cfg.stream = 0;
    cudaLaunchAttribute at[1];
    at[0].id = cudaLaunchAttributeProgrammaticStreamSerialization;
    at[0].val.programmaticStreamSerializationAllowed = 1;
    cfg.attrs = at;
    cfg.numAttrs = 1;
    cudaLaunchKernelEx(&cfg, kernel, args...);
}

extern "C" void kernel_launch(void* const* d_in, const int* in_sizes, int n_in,
                              void* d_out, int out_size) {
    const float* V   = (const float*)d_in[0];   // [4096]
    const float* obs = (const float*)d_in[1];   // [64,3]
    const float* pts = (const float*)d_in[2];   // [4096,3]
    const float* w   = (const float*)d_in[3];   // [4096]
    float* out = (float*)d_out;                 // [4,64,2]

    k_init<<<M_PTS / 256, 256>>>(V, pts, w);
    for (int it = 0; it < N_ITER; it++) {
        launch_pdl(k_acc, dim3(ROWBLK, JSPLIT), dim3(TPB));
        launch_pdl(k_update, dim3((NK * 2 * M_PTS) / 256), dim3(256));
    }
    launch_pdl(k_far, dim3(NDOBS), dim3(256), V, obs, w, out);
}

// round 11
// speedup vs baseline: 1.8331x; 1.0295x over previous
#include <cuda_runtime.h>
#include <math.h>

// ---------------------------------------------------------------------------
// LSForward: Born-series scattering, M=4096 pts, 4 wavenumbers (0.5*m), 5 iters.
// R11 = R10 minus fdouble_alu (measured net loss: acc 29.3->29.9, fma% down),
// plus jj-unroll 4 (8 independent pair-chains per warp to close the 13%
// latency gap vs the 26us FFMA-pipe-bound limit; issue 76.5% -> ~85%).
// PDL retained (proven -4us). Math identical to R3 (verified 4.7e-6).
// ---------------------------------------------------------------------------

constexpr int M_PTS  = 4096;
constexpr int NDOBS  = 64;
constexpr int NK     = 4;
constexpr int N_ITER = 5;

constexpr int TPB    = 128;                    // threads per block
constexpr int RPT    = 2;                      // rows per thread
constexpr int ROWBLK = M_PTS / (TPB * RPT);    // 16 row-blocks
constexpr int JSPLIT = 64;                     // j-partition count (grid.y)
constexpr int JCHUNK = M_PTS / JSPLIT;         // 64 j's per block

constexpr float C_G = 0.07957747154594767f;    // 1/(4*pi)

// Scratch (allocation-free: __device__ globals)
__device__ float g_px[M_PTS], g_py[M_PTS], g_pz[M_PTS];
__device__ float g_r2q[M_PTS];                     // 0.25*|p|^2
__device__ float g_vw[M_PTS];                      // 0.5*C_G * V * w (folded)
__device__ float g_p0[NK * 2 * M_PTS];
__device__ float g_p [NK * 2 * M_PTS];
__device__ float g_a [NK * 2 * M_PTS];             // folded matvec input
__device__ float g_part[JSPLIT][NK * 2 * M_PTS];   // deterministic j-partials (8 MB)

__device__ __forceinline__ float fsqrt_approx(float x) {
    float r; asm("sqrt.approx.f32 %0,%1;" : "=f"(r) : "f"(x)); return r;
}
__device__ __forceinline__ void pdl_wait() {
#if __CUDA_ARCH__ >= 900
    cudaGridDependencySynchronize();
#endif
}

// ---------------------------------------------------------------------------
__global__ void k_init(const float* __restrict__ V,
                       const float* __restrict__ pts,
                       const float* __restrict__ w) {
    int i = blockIdx.x * blockDim.x + threadIdx.x;
    if (i >= M_PTS) return;
    float x = pts[3 * i], y = pts[3 * i + 1], z = pts[3 * i + 2];
    g_px[i] = x; g_py[i] = y; g_pz[i] = z;
    g_r2q[i] = 0.25f * (x * x + y * y + z * z);
    float vw = 0.5f * C_G * V[i] * w[i];
    g_vw[i] = vw;
#pragma unroll
    for (int m = 0; m < NK; m++) {
        float kv = 0.5f * (float)(m + 1);
        float s, c;
        sincosf(kv * z, &s, &c);                   // accurate; one-time cost
        g_p0[m * 2 * M_PTS + i]          = c;
        g_p0[m * 2 * M_PTS + M_PTS + i]  = s;
        g_p [m * 2 * M_PTS + i]          = c;
        g_p [m * 2 * M_PTS + M_PTS + i]  = s;
        g_a [m * 2 * M_PTS + i]          = vw * c;
        g_a [m * 2 * M_PTS + M_PTS + i]  = vw * s;
    }
}

// ---------------------------------------------------------------------------
// Core Born matvec: grid (ROWBLK, JSPLIT), 256 rows x 64 j per block.
// Per pair: e = 0.25*d2 (R3-exact form: dot first, then ONE fused
// -0.5*dot + r2sum — numerically load-bearing near coincident points);
// theta = sqrt(e) = 0.5*D; sc = rsqrt(e) = 2/D with 0.5*C_G prefolded in a.
// Chebyshev G_m = sc * exp(i*m*theta).
// ---------------------------------------------------------------------------
__global__ __launch_bounds__(TPB) void k_acc() {
    __shared__ alignas(16) float sj[JCHUNK][12];  // px,py,pz,r2q, ar0,ai0..ar3,ai3

    pdl_wait();                                   // g_a/g_px from predecessor

    int t  = threadIdx.x;
    int j0 = blockIdx.y * JCHUNK;

    if (t < JCHUNK) {
        int j = j0 + t;
        sj[t][0] = g_px[j];
        sj[t][1] = g_py[j];
        sj[t][2] = g_pz[j];
        sj[t][3] = g_r2q[j];
#pragma unroll
        for (int m = 0; m < NK; m++) {
            sj[t][4 + 2 * m] = g_a[m * 2 * M_PTS + j];
            sj[t][5 + 2 * m] = g_a[m * 2 * M_PTS + M_PTS + j];
        }
    }
    __syncthreads();

    int rbase = blockIdx.x * (TPB * RPT) + t;
    float pix[RPT], piy[RPT], piz[RPT], r2i[RPT];
#pragma unroll
    for (int r = 0; r < RPT; r++) {
        int row = rbase + r * TPB;
        pix[r] = g_px[row]; piy[r] = g_py[row];
        piz[r] = g_pz[row]; r2i[r] = g_r2q[row];
    }

    float accr[RPT][NK], acci[RPT][NK];
#pragma unroll
    for (int r = 0; r < RPT; r++)
#pragma unroll
        for (int m = 0; m < NK; m++) { accr[r][m] = 0.f; acci[r][m] = 0.f; }

#pragma unroll 4
    for (int jj = 0; jj < JCHUNK; jj++) {
        float4 P  = *reinterpret_cast<const float4*>(&sj[jj][0]);
        float4 A0 = *reinterpret_cast<const float4*>(&sj[jj][4]);
        float4 A1 = *reinterpret_cast<const float4*>(&sj[jj][8]);
        int jg = j0 + jj;
#pragma unroll
        for (int r = 0; r < RPT; r++) {
            int row = rbase + r * TPB;
            float dot = fmaf(pix[r], P.x, fmaf(piy[r], P.y, piz[r] * P.z));
            float e   = fmaf(-0.5f, dot, r2i[r] + P.w);     // 0.25 * d2
            e = fmaxf(e, 2.5e-13f);
            float th  = fsqrt_approx(e);                    // 0.5 * D
            float sc  = rsqrtf(e);                          // 2/D (scale in a)
            sc = (row == jg) ? 0.f : sc;
            float s1, c1;
            __sincosf(th, &s1, &c1);
            float tc  = c1 + c1;
            // Chebyshev: G_m = sc * exp(i m theta)
            float g1r = sc * c1,             g1i = sc * s1;
            float g2r = fmaf(tc, g1r, -sc);  float g2i = tc * g1i;
            float g3r = fmaf(tc, g2r, -g1r); float g3i = fmaf(tc, g2i, -g1i);
            float g4r = fmaf(tc, g3r, -g2r); float g4i = fmaf(tc, g3i, -g2i);
            // complex MAC (negations free in FFMA modifiers)
            accr[r][0] = fmaf(g1r, A0.x, fmaf(-g1i, A0.y, accr[r][0]));
            acci[r][0] = fmaf(g1r, A0.y, fmaf( g1i, A0.x, acci[r][0]));
            accr[r][1] = fmaf(g2r, A0.z, fmaf(-g2i, A0.w, accr[r][1]));
            acci[r][1] = fmaf(g2r, A0.w, fmaf( g2i, A0.z, acci[r][1]));
            accr[r][2] = fmaf(g3r, A1.x, fmaf(-g3i, A1.y, accr[r][2]));
            acci[r][2] = fmaf(g3r, A1.y, fmaf( g3i, A1.x, acci[r][2]));
            accr[r][3] = fmaf(g4r, A1.z, fmaf(-g4i, A1.w, accr[r][3]));
            acci[r][3] = fmaf(g4r, A1.w, fmaf( g4i, A1.z, acci[r][3]));
        }
    }

    float* part = g_part[blockIdx.y];
#pragma unroll
    for (int r = 0; r < RPT; r++) {
        int row = rbase + r * TPB;
#pragma unroll
        for (int m = 0; m < NK; m++) {
            part[m * 2 * M_PTS + row]         = accr[r][m];
            part[m * 2 * M_PTS + M_PTS + row] = acci[r][m];
        }
    }
}

// ---------------------------------------------------------------------------
// Deterministic partial reduction + Born update: p = p0 + sum; a = vw*p.
// ---------------------------------------------------------------------------
__global__ void k_update() {
    pdl_wait();                                  // g_part from k_acc
    int e = blockIdx.x * blockDim.x + threadIdx.x;  // 0 .. NK*2*M-1
    float s = 0.f;
#pragma unroll 8
    for (int js = 0; js < JSPLIT; js++) s += g_part[js][e];
    float pv = g_p0[e] + s;
    g_p[e] = pv;
    g_a[e] = g_vw[e & (M_PTS - 1)] * pv;         // vw already 0.5*C_G*V*w
}

// ---------------------------------------------------------------------------
// Far-field: one block per observation direction.
// ---------------------------------------------------------------------------
__global__ __launch_bounds__(256) void k_far(const float* __restrict__ V,
                                             const float* __restrict__ obs,
                                             const float* __restrict__ w,
                                             float* __restrict__ out) {
    constexpr int FTPB = 256;
    pdl_wait();                                  // g_p from final k_update
    int d = blockIdx.x;
    int t = threadIdx.x;
    float ox = obs[3 * d], oy = obs[3 * d + 1], oz = obs[3 * d + 2];

    float fr[NK] = {0.f, 0.f, 0.f, 0.f};
    float fi[NK] = {0.f, 0.f, 0.f, 0.f};

    for (int j = t; j < M_PTS; j += FTPB) {
        float q = fmaf(g_px[j], ox, fmaf(g_py[j], oy, g_pz[j] * oz));
        float s1, c1;
        __sincosf(0.5f * q, &s1, &c1);
        float tc = c1 + c1;
        float cm[NK], sm[NK];
        cm[0] = c1;                      sm[0] = s1;
        cm[1] = fmaf(tc, c1, -1.f);      sm[1] = tc * s1;
        cm[2] = fmaf(tc, cm[1], -cm[0]); sm[2] = fmaf(tc, sm[1], -sm[0]);
        cm[3] = fmaf(tc, cm[2], -cm[1]); sm[3] = fmaf(tc, sm[2], -sm[1]);
        float v = V[j], wj = w[j];
#pragma unroll
        for (int m = 0; m < NK; m++) {
            float pr = g_p[m * 2 * M_PTS + j];
            float pi = g_p[m * 2 * M_PTS + M_PTS + j];
            float zr = v * pr, zi = v * pi;
            float ir = fmaf(zr, cm[m],  zi * sm[m]);   // exp(-ikQ)
            float ii = fmaf(zi, cm[m], -zr * sm[m]);
            fr[m] = fmaf(wj, ir, fr[m]);
            fi[m] = fmaf(wj, ii, fi[m]);
        }
    }

#pragma unroll
    for (int off = 16; off; off >>= 1) {
#pragma unroll
        for (int m = 0; m < NK; m++) {
            fr[m] += __shfl_down_sync(0xffffffffu, fr[m], off);
            fi[m] += __shfl_down_sync(0xffffffffu, fi[m], off);
        }
    }
    __shared__ float sred[8][FTPB / 32];
    int lane = t & 31, wid = t >> 5;
    if (lane == 0) {
#pragma unroll
        for (int m = 0; m < NK; m++) {
            sred[2 * m][wid]     = fr[m];
            sred[2 * m + 1][wid] = fi[m];
        }
    }
    __syncthreads();
    if (t < 8) {
        float s = 0.f;
#pragma unroll
        for (int wdx = 0; wdx < FTPB / 32; wdx++) s += sred[t][wdx];
        int m = t >> 1, c = t & 1;
        out[m * NDOBS * 2 + d * 2 + c] = -C_G * s;
    }
}

// ---------------------------------------------------------------------------
template <typename K, typename... Args>
static inline void launch_pdl(K kernel, dim3 grid, dim3 block, Args... args) {
    cudaLaunchConfig_t cfg = {};
    cfg.gridDim = grid;
    cfg.blockDim = block;
    cfg.dynamicSmemBytes = 0;
    cfg.stream = 0;
    cudaLaunchAttribute at[1];
    at[0].id = cudaLaunchAttributeProgrammaticStreamSerialization;
    at[0].val.programmaticStreamSerializationAllowed = 1;
    cfg.attrs = at;
    cfg.numAttrs = 1;
    cudaLaunchKernelEx(&cfg, kernel, args...);
}

extern "C" void kernel_launch(void* const* d_in, const int* in_sizes, int n_in,
                              void* d_out, int out_size) {
    const float* V   = (const float*)d_in[0];   // [4096]
    const float* obs = (const float*)d_in[1];   // [64,3]
    const float* pts = (const float*)d_in[2];   // [4096,3]
    const float* w   = (const float*)d_in[3];   // [4096]
    float* out = (float*)d_out;                 // [4,64,2]

    k_init<<<M_PTS / 256, 256>>>(V, pts, w);
    for (int it = 0; it < N_ITER; it++) {
        launch_pdl(k_acc, dim3(ROWBLK, JSPLIT), dim3(TPB));
        launch_pdl(k_update, dim3((NK * 2 * M_PTS) / 256), dim3(256));
    }
    launch_pdl(k_far, dim3(NDOBS), dim3(256), V, obs, w, out);
}